// round 16
// baseline (speedup 1.0000x reference)
#include <cuda_runtime.h>
#include <cstdint>

#define B_   8
#define CIN  96
#define CMID 48
#define HH   256
#define WW   256
#define H2   128
#define W2   128
#define CO   192

// conv1 output y in fp16: [b][oc][h][w], stored as half2 (adjacent pixels). 50 MB.
__device__ unsigned g_yh[B_ * CMID * HH * WW / 2];
// Pre-packed fp16 weights, LDS.64-pair layout:
// [chunk6][tap9][u4][oc*2+s], pitch 104 words; value = half2 of ic pair.
__device__ unsigned g_wph[6 * 3744];

__device__ __forceinline__ unsigned pack_h2(float lo, float hi) {
    unsigned r;
    asm("{ .reg .b16 l, h; cvt.rn.f16.f32 l, %1; cvt.rn.f16.f32 h, %2; "
        "mov.b32 %0, {l, h}; }" : "=r"(r) : "f"(lo), "f"(hi));
    return r;
}
__device__ __forceinline__ float2 h2f2(unsigned h) {
    float2 f;
    asm("{ .reg .b16 l, h; mov.b32 {l, h}, %2; "
        "cvt.f32.f16 %0, l; cvt.f32.f16 %1, h; }"
        : "=f"(f.x), "=f"(f.y) : "r"(h));
    return f;
}

__device__ __forceinline__ void mma_f16(float* c,
    unsigned a0, unsigned a1, unsigned a2, unsigned a3,
    unsigned b0, unsigned b1)
{
    asm volatile(
        "mma.sync.aligned.m16n8k16.row.col.f32.f16.f16.f32 "
        "{%0,%1,%2,%3}, {%4,%5,%6,%7}, {%8,%9}, {%0,%1,%2,%3};"
        : "+f"(c[0]), "+f"(c[1]), "+f"(c[2]), "+f"(c[3])
        : "r"(a0), "r"(a1), "r"(a2), "r"(a3), "r"(b0), "r"(b1));
}

__device__ __forceinline__ uint32_t smem_u32(const void* p) {
    uint32_t a;
    asm("{ .reg .u64 t; cvta.to.shared.u64 t, %1; cvt.u32.u64 %0, t; }"
        : "=r"(a) : "l"(p));
    return a;
}
#define CP_ASYNC16(dst, src) \
    asm volatile("cp.async.cg.shared.global [%0], [%1], 16;" \
                 :: "r"(dst), "l"(src))
#define CP_COMMIT() asm volatile("cp.async.commit_group;" ::: "memory")
#define CP_WAIT0()  asm volatile("cp.async.wait_group 0;" ::: "memory")

// ---------------------------------------------------------------------------
// Prepass (tiny): weights only, pair layout.
// ---------------------------------------------------------------------------
#define WN (6 * 9 * 8 * 48)
__global__ void prep_w_kernel(const float* __restrict__ w)
{
    int i = blockIdx.x * 256 + threadIdx.x;
    if (i >= WN) return;
    int chunk = i / 3456;
    int r  = i % 3456;
    int tap = r / 384;
    int r2  = r % 384;
    int icp = r2 / 48;
    int oc  = r2 % 48;
    int ic  = chunk * 16 + icp * 2;
    int u   = icp & 3;
    int s   = icp >> 2;
    g_wph[chunk * 3744 + (tap * 4 + u) * 104 + oc * 2 + s] =
        pack_h2(w[(oc * 96 + ic) * 9 + tap],
                w[(oc * 96 + ic + 1) * 9 + tap]);
}

// ---------------------------------------------------------------------------
// conv1: fp16 m16n8k16 implicit GEMM reading RAW fp32 x (no x prepass).
// Tile 64 cols x 4 rows, 256 thr / 8 warps, 2 CTAs/SM.
// Per chunk: cp.async fp32 (fs, single buf) + w -> wait -> convert fs->xs[buf]
// -> issue next chunk -> mma. fs layout: [ic16][r6][72 floats], col i = w0-4+i.
// xs: [icp8][r6][68 half2], col c = image col w0-1+c.
// ---------------------------------------------------------------------------
#define FS_WORDS (16 * 6 * 72)   // 6912 fp32
#define XS_WORDS (8 * 6 * 68)    // 3264 half2
#define WS_WORDS 3744
#define SMEM_SZ  ((FS_WORDS + 2 * XS_WORDS + 2 * WS_WORDS) * 4)  // 83712

__global__ __launch_bounds__(256, 2) void conv1_mma_kernel(
    const float* __restrict__ x)
{
    extern __shared__ unsigned sm[];
    float*    fs  = (float*)sm;                       // fp32 staging
    unsigned* xs0 = sm + FS_WORDS;                    // 2 x XS_WORDS
    unsigned* ws0 = sm + FS_WORDS + 2 * XS_WORDS;     // 2 x WS_WORDS

    const int tid  = threadIdx.x;
    const int lane = tid & 31;
    const int wid  = tid >> 5;
    const int g    = lane >> 2;
    const int u    = lane & 3;

    const int w0 = blockIdx.x * 64;
    const int h0 = blockIdx.y * 4;
    const int b  = blockIdx.z;

    const int wrow  = wid >> 1;          // 0..3
    const int wcolb = (wid & 1) * 32;    // 0 or 32

    const uint32_t fs_sm = smem_u32(fs);
    const uint32_t ws_sm = smem_u32(ws0);

    // uint4 column range within a 72-float row (edges predicated at borders)
    const int qlo = (blockIdx.x == 0) ? 1 : 0;
    const int qhi = (blockIdx.x == (WW / 64 - 1)) ? 17 : 18;

    auto issue = [&](int chunk, int buf) {
        // fp32 x: 96 rows (16 ic x 6 r) x 18 uint4; warp wid owns 12 rows
        #pragma unroll
        for (int k = 0; k < 7; k++) {           // 7*32 = 224 >= 216
            int j = k * 32 + lane;
            if (j >= 216) break;
            int kk = j / 18, q = j % 18;
            int rowid = wid + kk * 8;           // 0..95
            int ic = rowid / 6, r = rowid % 6;
            int gr = h0 - 1 + r;
            if ((unsigned)gr < (unsigned)HH && q >= qlo && q < qhi) {
                const float* src =
                    x + ((size_t)((b * CIN + chunk * 16 + ic) * HH + gr)) * WW
                      + (w0 - 4);
                CP_ASYNC16(fs_sm + (rowid * 72 + q * 4) * 4, src + q * 4);
            }
        }
        // weights: 936 uint4, warp wid owns 117
        const unsigned* wsrc = g_wph + chunk * 3744;
        uint32_t wd = ws_sm + buf * WS_WORDS * 4;
        for (int j = lane; j < 117; j += 32) {
            int k = wid * 117 + j;
            CP_ASYNC16(wd + k * 16, wsrc + k * 4);
        }
    };

    auto convert = [&](int buf) {
        unsigned* xsb = xs0 + buf * XS_WORDS;
        #pragma unroll
        for (int k = 0; k < 6; k++) {
            int co = wid + k * 8;               // 0..47 = icp*6 + r
            int icp = co / 6, r = co - icp * 6;
            bool rok = ((unsigned)(h0 - 1 + r) < (unsigned)HH);
            const float* s0 = fs + (icp * 12 + r) * 72 + 3;
            const float* s1 = s0 + 432;         // +6*72 (next ic)
            unsigned* d = xsb + co * 68;
            #pragma unroll
            for (int cc = 0; cc < 3; cc++) {
                int c = cc * 32 + lane;
                if (c >= 68) break;
                bool ok = rok && ((unsigned)(w0 - 1 + c) < (unsigned)WW);
                float f0 = ok ? s0[c] : 0.f;
                float f1 = ok ? s1[c] : 0.f;
                d[c] = pack_h2(ok ? f0 : 0.f, ok ? f1 : 0.f);
            }
        }
    };

    float acc[2][6][4];
    #pragma unroll
    for (int t = 0; t < 2; t++)
        #pragma unroll
        for (int n = 0; n < 6; n++)
            #pragma unroll
            for (int k = 0; k < 4; k++)
                acc[t][n][k] = 0.f;

    issue(0, 0);
    CP_COMMIT();

    for (int chunk = 0; chunk < 6; chunk++) {
        const int buf = chunk & 1;
        CP_WAIT0();
        __syncthreads();          // fs + ws[buf] visible to all threads
        convert(buf);
        __syncthreads();          // xs[buf] ready; fs free for reuse
        if (chunk < 5) {
            issue(chunk + 1, buf ^ 1);
            CP_COMMIT();
        }

        const unsigned* xsb = xs0 + buf * XS_WORDS;
        const unsigned* wsb = ws0 + buf * WS_WORDS;

        #pragma unroll
        for (int tap = 0; tap < 9; tap++) {
            const int kh = tap / 3, kw = tap % 3;
            const int xr = wrow + kh;

            unsigned bf[6][2];
            #pragma unroll
            for (int n = 0; n < 6; n++) {
                uint2 wv = *(const uint2*)
                    &wsb[(tap * 4 + u) * 104 + (n * 8 + g) * 2];
                bf[n][0] = wv.x;
                bf[n][1] = wv.y;
            }
            #pragma unroll
            for (int t = 0; t < 2; t++) {
                const int colc = wcolb + t * 16 + g + kw;
                unsigned a0 = xsb[(u * 6 + xr) * 68 + colc];
                unsigned a1 = xsb[(u * 6 + xr) * 68 + colc + 8];
                unsigned a2 = xsb[((u + 4) * 6 + xr) * 68 + colc];
                unsigned a3 = xsb[((u + 4) * 6 + xr) * 68 + colc + 8];
                #pragma unroll
                for (int n = 0; n < 6; n++)
                    mma_f16(acc[t][n], a0, a1, a2, a3, bf[n][0], bf[n][1]);
            }
        }
        __syncthreads();          // all warps done reading xs/ws[buf]
    }

    // ---- store y fp16 half2 (pair lanes g, g^1 = adjacent pixels) ----
    #pragma unroll
    for (int t = 0; t < 2; t++) {
        const int col = wcolb + t * 16 + g;
        const int h   = h0 + wrow;
        const int hc  = (w0 + col) >> 1;
        #pragma unroll
        for (int n = 0; n < 6; n++) {
            const int oc = n * 8 + 2 * u;
            float q0 = __shfl_xor_sync(0xffffffffu, acc[t][n][0], 4);
            float q1 = __shfl_xor_sync(0xffffffffu, acc[t][n][1], 4);
            float q2 = __shfl_xor_sync(0xffffffffu, acc[t][n][2], 4);
            float q3 = __shfl_xor_sync(0xffffffffu, acc[t][n][3], 4);
            if (!(g & 1)) {
                unsigned* base =
                    g_yh + ((size_t)(b * CMID + oc) * HH + h) * 128 + hc;
                base[0]                       = pack_h2(acc[t][n][0], q0);
                base[(size_t)HH * WW / 2]     = pack_h2(acc[t][n][1], q1);
                base[4]                       = pack_h2(acc[t][n][2], q2);
                base[(size_t)HH * WW / 2 + 4] = pack_h2(acc[t][n][3], q3);
            }
        }
    }
}

// ---------------------------------------------------------------------------
// Kernel B (R12 exact, proven 55us): fused pixel_unshuffle + mask interleave
// + grouped 3x3 conv. CTA: 16 rows x 128 cols, thread 2x4.
// ---------------------------------------------------------------------------
__global__ __launch_bounds__(256) void conv2_kernel(
    const float* __restrict__ mask, const float* __restrict__ wp,
    float* __restrict__ out)
{
    __shared__ __align__(16) float sy[2][18][132];
    __shared__ __align__(16) float smm[2][18][132];
    __shared__ float swp[36];

    const int tid = threadIdx.x;
    const int hb  = blockIdx.x * 16;
    const int gp  = blockIdx.y;     // (c, dy)
    const int b   = blockIdx.z;
    const int c   = gp >> 1;
    const int dy  = gp & 1;
    const int g0  = 4 * c + 2 * dy;

    if (tid < 36) swp[tid] = wp[g0 * 18 + tid];

    #pragma unroll
    for (int it = 0; it < 5; it++) {
        int idx = it * 256 + tid;
        if (idx < 1152) {
            int r  = idx >> 6;
            int q2 = (idx & 63) * 2;
            int gy = 2 * (hb - 1 + r) + dy;
            uint2 yv = make_uint2(0u, 0u);
            float4 mv = make_float4(0.f, 0.f, 0.f, 0.f);
            if ((unsigned)gy < (unsigned)HH) {
                yv = *(const uint2*)&g_yh[((size_t)(b * CMID + c) * HH + gy) * 128 + q2];
                mv = *(const float4*)&mask[((size_t)(b * HH) + gy) * WW + 2 * q2];
            }
            float2 f0 = h2f2(yv.x), f1 = h2f2(yv.y);
            sy[0][r][1 + q2] = f0.x;  sy[1][r][1 + q2] = f0.y;
            sy[0][r][2 + q2] = f1.x;  sy[1][r][2 + q2] = f1.y;
            smm[0][r][1 + q2] = mv.x; smm[1][r][1 + q2] = mv.y;
            smm[0][r][2 + q2] = mv.z; smm[1][r][2 + q2] = mv.w;
        }
    }
    if (tid < 18) {
        sy[0][tid][0] = 0.f;   sy[1][tid][0] = 0.f;
        sy[0][tid][129] = 0.f; sy[1][tid][129] = 0.f;
        smm[0][tid][0] = 0.f;   smm[1][tid][0] = 0.f;
        smm[0][tid][129] = 0.f; smm[1][tid][129] = 0.f;
    }
    __syncthreads();

    const int rr  = tid >> 5;
    const int w0c = (tid & 31) * 4;

    float a[2][2][4];
    #pragma unroll
    for (int o = 0; o < 2; o++)
        #pragma unroll
        for (int gx = 0; gx < 2; gx++)
            #pragma unroll
            for (int p = 0; p < 4; p++)
                a[o][gx][p] = 0.f;

    #pragma unroll
    for (int r = 0; r < 4; r++) {
        const int sr = 2 * rr + r;
        float4 ya0 = *(const float4*)&sy[0][sr][w0c];
        float2 yb0 = *(const float2*)&sy[0][sr][w0c + 4];
        float4 ya1 = *(const float4*)&sy[1][sr][w0c];
        float2 yb1 = *(const float2*)&sy[1][sr][w0c + 4];
        float4 ma0 = *(const float4*)&smm[0][sr][w0c];
        float2 mb0 = *(const float2*)&smm[0][sr][w0c + 4];
        float4 ma1 = *(const float4*)&smm[1][sr][w0c];
        float2 mb1 = *(const float2*)&smm[1][sr][w0c + 4];
        float yv0[6] = {ya0.x, ya0.y, ya0.z, ya0.w, yb0.x, yb0.y};
        float yv1[6] = {ya1.x, ya1.y, ya1.z, ya1.w, yb1.x, yb1.y};
        float mv0[6] = {ma0.x, ma0.y, ma0.z, ma0.w, mb0.x, mb0.y};
        float mv1[6] = {ma1.x, ma1.y, ma1.z, ma1.w, mb1.x, mb1.y};

        #pragma unroll
        for (int orow = 0; orow < 2; orow++) {
            const int kh = r - orow;
            if (kh < 0 || kh > 2) continue;
            #pragma unroll
            for (int kw = 0; kw < 3; kw++) {
                float wy0 = swp[kh * 3 + kw];
                float wm0 = swp[9 + kh * 3 + kw];
                float wy1 = swp[18 + kh * 3 + kw];
                float wm1 = swp[27 + kh * 3 + kw];
                #pragma unroll
                for (int p = 0; p < 4; p++) {
                    a[orow][0][p] = fmaf(wy0, yv0[kw + p], a[orow][0][p]);
                    a[orow][0][p] = fmaf(wm0, mv0[kw + p], a[orow][0][p]);
                    a[orow][1][p] = fmaf(wy1, yv1[kw + p], a[orow][1][p]);
                    a[orow][1][p] = fmaf(wm1, mv1[kw + p], a[orow][1][p]);
                }
            }
        }
    }

    #pragma unroll
    for (int orow = 0; orow < 2; orow++) {
        const int h = hb + 2 * rr + orow;
        *(float4*)&out[((size_t)(b * CO + g0) * H2 + h) * W2 + w0c] =
            make_float4(a[orow][0][0], a[orow][0][1], a[orow][0][2], a[orow][0][3]);
        *(float4*)&out[((size_t)(b * CO + g0 + 1) * H2 + h) * W2 + w0c] =
            make_float4(a[orow][1][0], a[orow][1][1], a[orow][1][2], a[orow][1][3]);
    }
}

// ---------------------------------------------------------------------------
extern "C" void kernel_launch(void* const* d_in, const int* in_sizes, int n_in,
                              void* d_out, int out_size)
{
    const float* x      = (const float*)d_in[0];
    const float* mask   = (const float*)d_in[1];
    const float* w_body = (const float*)d_in[2];
    const float* w_proj = (const float*)d_in[3];
    float* out = (float*)d_out;

    cudaFuncSetAttribute(conv1_mma_kernel,
                         cudaFuncAttributeMaxDynamicSharedMemorySize, SMEM_SZ);

    prep_w_kernel<<<(WN + 255) / 256, 256>>>(w_body);

    dim3 g1(WW / 64, HH / 4, B_);       // (4, 64, 8) = 2048 CTAs
    conv1_mma_kernel<<<g1, 256, SMEM_SZ>>>(x);

    dim3 g2(H2 / 16, 96, B_);           // (8, 96, 8) = 6144 CTAs
    conv2_kernel<<<g2, 256>>>(mask, w_proj, out);
}

// round 17
// speedup vs baseline: 1.1381x; 1.1381x over previous
#include <cuda_runtime.h>
#include <cstdint>

#define B_   8
#define CIN  96
#define CMID 48
#define HH   256
#define WW   256
#define H2   128
#define W2   128
#define CO   192

// conv1 output y in fp16: [b][oc][h][w], stored as half2 (adjacent pixels). 50 MB.
__device__ unsigned g_yh[B_ * CMID * HH * WW / 2];
// Pre-packed fp16 weights, LDS.64-pair layout:
// [chunk6][tap9][u4][oc*2+s], pitch 104 words; value = half2 of ic pair.
__device__ unsigned g_wph[6 * 3744];

__device__ __forceinline__ unsigned pack_h2(float lo, float hi) {
    unsigned r;
    asm("{ .reg .b16 l, h; cvt.rn.f16.f32 l, %1; cvt.rn.f16.f32 h, %2; "
        "mov.b32 %0, {l, h}; }" : "=r"(r) : "f"(lo), "f"(hi));
    return r;
}
__device__ __forceinline__ float2 h2f2(unsigned h) {
    float2 f;
    asm("{ .reg .b16 l, h; mov.b32 {l, h}, %2; "
        "cvt.f32.f16 %0, l; cvt.f32.f16 %1, h; }"
        : "=f"(f.x), "=f"(f.y) : "r"(h));
    return f;
}

__device__ __forceinline__ void mma_f16(float* c,
    unsigned a0, unsigned a1, unsigned a2, unsigned a3,
    unsigned b0, unsigned b1)
{
    asm volatile(
        "mma.sync.aligned.m16n8k16.row.col.f32.f16.f16.f32 "
        "{%0,%1,%2,%3}, {%4,%5,%6,%7}, {%8,%9}, {%0,%1,%2,%3};"
        : "+f"(c[0]), "+f"(c[1]), "+f"(c[2]), "+f"(c[3])
        : "r"(a0), "r"(a1), "r"(a2), "r"(a3), "r"(b0), "r"(b1));
}

__device__ __forceinline__ uint32_t smem_u32(const void* p) {
    uint32_t a;
    asm("{ .reg .u64 t; cvta.to.shared.u64 t, %1; cvt.u32.u64 %0, t; }"
        : "=r"(a) : "l"(p));
    return a;
}
#define CP_ASYNC16(dst, src) \
    asm volatile("cp.async.cg.shared.global [%0], [%1], 16;" \
                 :: "r"(dst), "l"(src))
#define CP_COMMIT() asm volatile("cp.async.commit_group;" ::: "memory")
#define CP_WAIT0()  asm volatile("cp.async.wait_group 0;" ::: "memory")

// ---------------------------------------------------------------------------
// Prepass (tiny): weights only, pair layout.
// ---------------------------------------------------------------------------
#define WN (6 * 9 * 8 * 48)
__global__ void prep_w_kernel(const float* __restrict__ w)
{
    int i = blockIdx.x * 256 + threadIdx.x;
    if (i >= WN) return;
    int chunk = i / 3456;
    int r  = i % 3456;
    int tap = r / 384;
    int r2  = r % 384;
    int icp = r2 / 48;
    int oc  = r2 % 48;
    int ic  = chunk * 16 + icp * 2;
    int u   = icp & 3;
    int s   = icp >> 2;
    g_wph[chunk * 3744 + (tap * 4 + u) * 104 + oc * 2 + s] =
        pack_h2(w[(oc * 96 + ic) * 9 + tap],
                w[(oc * 96 + ic + 1) * 9 + tap]);
}

// ---------------------------------------------------------------------------
// conv1: fp16 m16n8k16 implicit GEMM, register-resident x staging.
// Tile 64 cols x 4 rows, 256 thr / 8 warps, 2 CTAs/SM.
// Per chunk: LDG fp32 for chunk+1 into regs -> mma (hides DRAM latency)
// -> pack+STS into xs[buf^1] -> sync. No fp32 smem buffer.
// xs: [co48 = icp*6+r][68 half2], col c = image col w0-1+c.
// ---------------------------------------------------------------------------
#define XS_WORDS (48 * 68)       // 3264 half2
#define WS_WORDS 3744
#define NSLOT    13              // ceil(3264 / 256)
#define SMEM_SZ  ((2 * XS_WORDS + 2 * WS_WORDS) * 4)   // 56064

__global__ __launch_bounds__(256, 2) void conv1_mma_kernel(
    const float* __restrict__ x)
{
    extern __shared__ unsigned sm[];
    unsigned* xs0 = sm;                    // 2 x XS_WORDS
    unsigned* ws0 = sm + 2 * XS_WORDS;     // 2 x WS_WORDS

    const int tid  = threadIdx.x;
    const int lane = tid & 31;
    const int wid  = tid >> 5;
    const int g    = lane >> 2;
    const int u    = lane & 3;

    const int w0 = blockIdx.x * 64;
    const int h0 = blockIdx.y * 4;
    const int b  = blockIdx.z;

    const int wrow  = wid >> 1;          // 0..3
    const int wcolb = (wid & 1) * 32;    // 0 or 32

    const uint32_t ws_sm = smem_u32(ws0);

    // Per-thread slot geometry (constant across chunks)
    int s_co[NSLOT], s_gc[NSLOT];
    bool s_ok[NSLOT];
    #pragma unroll
    for (int s = 0; s < NSLOT; s++) {
        int idx = s * 256 + tid;
        int co  = idx / 68;
        int c   = idx - co * 68;
        int icp = co / 6, r = co - icp * 6;
        int gr  = h0 - 1 + r;
        int gc  = w0 - 1 + c;
        s_co[s] = co;
        s_gc[s] = ((b * CIN + icp * 2) * HH + gr) * WW + gc;
        s_ok[s] = (co < 48) && ((unsigned)gr < (unsigned)HH) &&
                  ((unsigned)gc < (unsigned)WW);
    }

    auto ldg_chunk = [&](int chunk, float* v) {
        const float* xb = x + (size_t)chunk * 16 * HH * WW;
        #pragma unroll
        for (int s = 0; s < NSLOT; s++) {
            float f0 = 0.f, f1 = 0.f;
            if (s_ok[s]) {
                f0 = __ldg(xb + s_gc[s]);
                f1 = __ldg(xb + s_gc[s] + HH * WW);
            }
            v[2 * s]     = f0;
            v[2 * s + 1] = f1;
        }
    };
    auto sts_chunk = [&](int buf, const float* v) {
        unsigned* xsb = xs0 + buf * XS_WORDS;
        #pragma unroll
        for (int s = 0; s < NSLOT; s++) {
            int idx = s * 256 + tid;
            if (idx < XS_WORDS)
                xsb[idx] = pack_h2(v[2 * s], v[2 * s + 1]);
        }
    };
    auto issue_w = [&](int chunk, int buf) {
        const unsigned* wsrc = g_wph + chunk * 3744;
        uint32_t wd = ws_sm + buf * WS_WORDS * 4;
        for (int j = lane; j < 117; j += 32) {
            int k = wid * 117 + j;
            CP_ASYNC16(wd + k * 16, wsrc + k * 4);
        }
    };

    float acc[2][6][4];
    #pragma unroll
    for (int t = 0; t < 2; t++)
        #pragma unroll
        for (int n = 0; n < 6; n++)
            #pragma unroll
            for (int k = 0; k < 4; k++)
                acc[t][n][k] = 0.f;

    float v[2 * NSLOT];

    // ---- prologue: chunk 0 staged serially (one-time cost) ----
    ldg_chunk(0, v);
    issue_w(0, 0);
    CP_COMMIT();
    sts_chunk(0, v);
    CP_WAIT0();
    __syncthreads();

    for (int chunk = 0; chunk < 6; chunk++) {
        const int buf = chunk & 1;
        if (chunk < 5) {
            ldg_chunk(chunk + 1, v);     // in-flight across the mma block
            issue_w(chunk + 1, buf ^ 1);
            CP_COMMIT();
        }

        const unsigned* xsb = xs0 + buf * XS_WORDS;
        const unsigned* wsb = ws0 + buf * WS_WORDS;

        #pragma unroll
        for (int tap = 0; tap < 9; tap++) {
            const int kh = tap / 3, kw = tap % 3;
            const int xr = wrow + kh;

            unsigned bf[6][2];
            #pragma unroll
            for (int n = 0; n < 6; n++) {
                uint2 wv = *(const uint2*)
                    &wsb[(tap * 4 + u) * 104 + (n * 8 + g) * 2];
                bf[n][0] = wv.x;
                bf[n][1] = wv.y;
            }
            #pragma unroll
            for (int t = 0; t < 2; t++) {
                const int colc = wcolb + t * 16 + g + kw;
                unsigned a0 = xsb[(u * 6 + xr) * 68 + colc];
                unsigned a1 = xsb[(u * 6 + xr) * 68 + colc + 8];
                unsigned a2 = xsb[((u + 4) * 6 + xr) * 68 + colc];
                unsigned a3 = xsb[((u + 4) * 6 + xr) * 68 + colc + 8];
                #pragma unroll
                for (int n = 0; n < 6; n++)
                    mma_f16(acc[t][n], a0, a1, a2, a3, bf[n][0], bf[n][1]);
            }
        }

        if (chunk < 5) {
            sts_chunk(buf ^ 1, v);       // xs[buf^1] free since prev barrier
            CP_WAIT0();
            __syncthreads();             // xs/ws[buf^1] ready for next iter
        }
    }

    // ---- store y fp16 half2 (pair lanes g, g^1 = adjacent pixels) ----
    #pragma unroll
    for (int t = 0; t < 2; t++) {
        const int col = wcolb + t * 16 + g;
        const int h   = h0 + wrow;
        const int hc  = (w0 + col) >> 1;
        #pragma unroll
        for (int n = 0; n < 6; n++) {
            const int oc = n * 8 + 2 * u;
            float q0 = __shfl_xor_sync(0xffffffffu, acc[t][n][0], 4);
            float q1 = __shfl_xor_sync(0xffffffffu, acc[t][n][1], 4);
            float q2 = __shfl_xor_sync(0xffffffffu, acc[t][n][2], 4);
            float q3 = __shfl_xor_sync(0xffffffffu, acc[t][n][3], 4);
            if (!(g & 1)) {
                unsigned* base =
                    g_yh + ((size_t)(b * CMID + oc) * HH + h) * 128 + hc;
                base[0]                       = pack_h2(acc[t][n][0], q0);
                base[(size_t)HH * WW / 2]     = pack_h2(acc[t][n][1], q1);
                base[4]                       = pack_h2(acc[t][n][2], q2);
                base[(size_t)HH * WW / 2 + 4] = pack_h2(acc[t][n][3], q3);
            }
        }
    }
}

// ---------------------------------------------------------------------------
// Kernel B (R12 exact, proven 55us): fused pixel_unshuffle + mask interleave
// + grouped 3x3 conv. CTA: 16 rows x 128 cols, thread 2x4.
// ---------------------------------------------------------------------------
__global__ __launch_bounds__(256) void conv2_kernel(
    const float* __restrict__ mask, const float* __restrict__ wp,
    float* __restrict__ out)
{
    __shared__ __align__(16) float sy[2][18][132];
    __shared__ __align__(16) float smm[2][18][132];
    __shared__ float swp[36];

    const int tid = threadIdx.x;
    const int hb  = blockIdx.x * 16;
    const int gp  = blockIdx.y;     // (c, dy)
    const int b   = blockIdx.z;
    const int c   = gp >> 1;
    const int dy  = gp & 1;
    const int g0  = 4 * c + 2 * dy;

    if (tid < 36) swp[tid] = wp[g0 * 18 + tid];

    #pragma unroll
    for (int it = 0; it < 5; it++) {
        int idx = it * 256 + tid;
        if (idx < 1152) {
            int r  = idx >> 6;
            int q2 = (idx & 63) * 2;
            int gy = 2 * (hb - 1 + r) + dy;
            uint2 yv = make_uint2(0u, 0u);
            float4 mv = make_float4(0.f, 0.f, 0.f, 0.f);
            if ((unsigned)gy < (unsigned)HH) {
                yv = *(const uint2*)&g_yh[((size_t)(b * CMID + c) * HH + gy) * 128 + q2];
                mv = *(const float4*)&mask[((size_t)(b * HH) + gy) * WW + 2 * q2];
            }
            float2 f0 = h2f2(yv.x), f1 = h2f2(yv.y);
            sy[0][r][1 + q2] = f0.x;  sy[1][r][1 + q2] = f0.y;
            sy[0][r][2 + q2] = f1.x;  sy[1][r][2 + q2] = f1.y;
            smm[0][r][1 + q2] = mv.x; smm[1][r][1 + q2] = mv.y;
            smm[0][r][2 + q2] = mv.z; smm[1][r][2 + q2] = mv.w;
        }
    }
    if (tid < 18) {
        sy[0][tid][0] = 0.f;   sy[1][tid][0] = 0.f;
        sy[0][tid][129] = 0.f; sy[1][tid][129] = 0.f;
        smm[0][tid][0] = 0.f;   smm[1][tid][0] = 0.f;
        smm[0][tid][129] = 0.f; smm[1][tid][129] = 0.f;
    }
    __syncthreads();

    const int rr  = tid >> 5;
    const int w0c = (tid & 31) * 4;

    float a[2][2][4];
    #pragma unroll
    for (int o = 0; o < 2; o++)
        #pragma unroll
        for (int gx = 0; gx < 2; gx++)
            #pragma unroll
            for (int p = 0; p < 4; p++)
                a[o][gx][p] = 0.f;

    #pragma unroll
    for (int r = 0; r < 4; r++) {
        const int sr = 2 * rr + r;
        float4 ya0 = *(const float4*)&sy[0][sr][w0c];
        float2 yb0 = *(const float2*)&sy[0][sr][w0c + 4];
        float4 ya1 = *(const float4*)&sy[1][sr][w0c];
        float2 yb1 = *(const float2*)&sy[1][sr][w0c + 4];
        float4 ma0 = *(const float4*)&smm[0][sr][w0c];
        float2 mb0 = *(const float2*)&smm[0][sr][w0c + 4];
        float4 ma1 = *(const float4*)&smm[1][sr][w0c];
        float2 mb1 = *(const float2*)&smm[1][sr][w0c + 4];
        float yv0[6] = {ya0.x, ya0.y, ya0.z, ya0.w, yb0.x, yb0.y};
        float yv1[6] = {ya1.x, ya1.y, ya1.z, ya1.w, yb1.x, yb1.y};
        float mv0[6] = {ma0.x, ma0.y, ma0.z, ma0.w, mb0.x, mb0.y};
        float mv1[6] = {ma1.x, ma1.y, ma1.z, ma1.w, mb1.x, mb1.y};

        #pragma unroll
        for (int orow = 0; orow < 2; orow++) {
            const int kh = r - orow;
            if (kh < 0 || kh > 2) continue;
            #pragma unroll
            for (int kw = 0; kw < 3; kw++) {
                float wy0 = swp[kh * 3 + kw];
                float wm0 = swp[9 + kh * 3 + kw];
                float wy1 = swp[18 + kh * 3 + kw];
                float wm1 = swp[27 + kh * 3 + kw];
                #pragma unroll
                for (int p = 0; p < 4; p++) {
                    a[orow][0][p] = fmaf(wy0, yv0[kw + p], a[orow][0][p]);
                    a[orow][0][p] = fmaf(wm0, mv0[kw + p], a[orow][0][p]);
                    a[orow][1][p] = fmaf(wy1, yv1[kw + p], a[orow][1][p]);
                    a[orow][1][p] = fmaf(wm1, mv1[kw + p], a[orow][1][p]);
                }
            }
        }
    }

    #pragma unroll
    for (int orow = 0; orow < 2; orow++) {
        const int h = hb + 2 * rr + orow;
        *(float4*)&out[((size_t)(b * CO + g0) * H2 + h) * W2 + w0c] =
            make_float4(a[orow][0][0], a[orow][0][1], a[orow][0][2], a[orow][0][3]);
        *(float4*)&out[((size_t)(b * CO + g0 + 1) * H2 + h) * W2 + w0c] =
            make_float4(a[orow][1][0], a[orow][1][1], a[orow][1][2], a[orow][1][3]);
    }
}

// ---------------------------------------------------------------------------
extern "C" void kernel_launch(void* const* d_in, const int* in_sizes, int n_in,
                              void* d_out, int out_size)
{
    const float* x      = (const float*)d_in[0];
    const float* mask   = (const float*)d_in[1];
    const float* w_body = (const float*)d_in[2];
    const float* w_proj = (const float*)d_in[3];
    float* out = (float*)d_out;

    cudaFuncSetAttribute(conv1_mma_kernel,
                         cudaFuncAttributeMaxDynamicSharedMemorySize, SMEM_SZ);

    prep_w_kernel<<<(WN + 255) / 256, 256>>>(w_body);

    dim3 g1(WW / 64, HH / 4, B_);       // (4, 64, 8) = 2048 CTAs
    conv1_mma_kernel<<<g1, 256, SMEM_SZ>>>(x);

    dim3 g2(H2 / 16, 96, B_);           // (8, 96, 8) = 6144 CTAs
    conv2_kernel<<<g2, 256>>>(mask, w_proj, out);
}